// round 16
// baseline (speedup 1.0000x reference)
#include <cuda_runtime.h>
#include <cuda_fp16.h>
#include <cstdint>
#include <stddef.h>
#include <math.h>

#define B_DIM 1024
#define L_DIM 1024
#define O_DIM 4096
#define N_ITERS 20
#define INF_LR   0.01f
#define SPARSE_Z 1e-3f

typedef unsigned short u16;
typedef uint32_t u32;

// ---------------- scratch (no cudaMalloc allowed) ----------------
__device__ u16   g_Wh  [O_DIM * L_DIM];
__device__ u16   g_WTh [L_DIM * O_DIM];
__device__ u16   g_Gh  [B_DIM * O_DIM];
__device__ float g_zf  [B_DIM * L_DIM];
__device__ u16   g_zh  [B_DIM * L_DIM];
__device__ float g_part[4 * B_DIM * L_DIM];   // split-K partials (16MB)

// ---------------- helpers ----------------
__device__ __forceinline__ u32 smem_u32(const void* p) {
    u32 a;
    asm("{ .reg .u64 t; cvta.to.shared.u64 t, %1; cvt.u32.u64 %0, t; }" : "=r"(a) : "l"(p));
    return a;
}
__device__ __forceinline__ void cp16(u32 dst, const void* src) {
    asm volatile("cp.async.cg.shared.global [%0], [%1], 16;" :: "r"(dst), "l"(src));
}
__device__ __forceinline__ void cp_commit() { asm volatile("cp.async.commit_group;"); }
template <int N> __device__ __forceinline__ void cp_wait() {
    asm volatile("cp.async.wait_group %0;" :: "n"(N));
}
__device__ __forceinline__ void ldsm4(u32* r, u32 a) {
    asm volatile("ldmatrix.sync.aligned.m8n8.x4.shared.b16 {%0,%1,%2,%3}, [%4];"
                 : "=r"(r[0]), "=r"(r[1]), "=r"(r[2]), "=r"(r[3]) : "r"(a));
}
__device__ __forceinline__ void mma_f16(float* d, const u32* a, u32 b0, u32 b1) {
    asm volatile(
        "mma.sync.aligned.m16n8k16.row.col.f32.f16.f16.f32 "
        "{%0,%1,%2,%3},{%4,%5,%6,%7},{%8,%9},{%0,%1,%2,%3};"
        : "+f"(d[0]), "+f"(d[1]), "+f"(d[2]), "+f"(d[3])
        : "r"(a[0]), "r"(a[1]), "r"(a[2]), "r"(a[3]), "r"(b0), "r"(b1));
}
__device__ __forceinline__ u16 f2h(float v) {
    return __half_as_ushort(__float2half_rn(v));
}
__device__ __forceinline__ u32 swz(u32 off) { return off ^ ((off >> 3) & 0x70u); }

// ---------------- one-time prep ----------------
__global__ void prep_w(const float* __restrict__ W,
                       u16* __restrict__ Wh, u16* __restrict__ WTh) {
    __shared__ float t[32][33];
    int tx = threadIdx.x, ty = threadIdx.y;
    int lx = blockIdx.x * 32, oy = blockIdx.y * 32;
#pragma unroll
    for (int r = 0; r < 32; r += 8) {
        size_t idx = (size_t)(oy + ty + r) * L_DIM + lx + tx;
        float v = W[idx];
        Wh[idx] = f2h(v);
        t[ty + r][tx] = v;
    }
    __syncthreads();
#pragma unroll
    for (int r = 0; r < 32; r += 8) {
        float v = t[tx][ty + r];
        size_t idx = (size_t)(lx + ty + r) * O_DIM + oy + tx;
        WTh[idx] = f2h(v);
    }
}

__global__ void init_z(const float* __restrict__ mu, float* __restrict__ zf,
                       u16* __restrict__ zh) {
    int i = blockIdx.x * blockDim.x + threadIdx.x;
    float v = mu[i & (L_DIM - 1)];
    zf[i] = v;
    zh[i] = f2h(v);
}

// ---- fp16 GEMM, CTA 128x256 (256 thr, 2x4 warps, warp tile 64x64) ----------
// R11/R15 geometry + REGISTER FRAGMENT DOUBLE-BUFFERING: each ks-step issues
// next-step's 8 ldsm before this step's 32 MMAs, hiding the ldsm->mma RAW
// (the only stall 2 warps/SMSP cannot hide by warp switching).
// EPI=1: p=tanh(C); g=(1-p^2)*(X-p); write g as fp16 (Oh).
// EPI=0: write raw fp32 partial to OF1 + blockIdx.z*(B*L).
template <int EPI, int KROW, int KLEN>
__global__ void __launch_bounds__(256, 1)
gemm_big(const u16* __restrict__ Ah, const u16* __restrict__ Bh,
         const float* __restrict__ X,
         u16* __restrict__ Oh, float* __restrict__ OF1) {
    constexpr int BM = 128, BN = 256, BK = 64, ROWB = 128;
    constexpr int ABYTES = BM * ROWB;          // 16384
    constexpr int BBYTES = BN * ROWB;          // 32768
    constexpr int STAGE  = ABYTES + BBYTES;    // 49152
    constexpr int CPA = ABYTES / 16, CPB = BBYTES / 16;
    constexpr int TOT = CPA + CPB;             // 3072
    constexpr int S = KLEN / BK;               // 16
    constexpr int ZN = B_DIM * L_DIM;

    extern __shared__ char sraw[];
    const u32 smem0 = (smem_u32(sraw) + 127u) & ~127u;

    const int tid = threadIdx.x, lane = tid & 31, wid = tid >> 5;
    const int wm = wid >> 2, wn = wid & 3;     // 2 x 4 warps, warp tile 64x64
    const int bm = blockIdx.y * BM, bn = blockIdx.x * BN;
    const int kbase = blockIdx.z * S;

    auto load_stage = [&](int s, int buf) {
        const u32 sb = smem0 + (u32)buf * STAGE;
        const int k0 = (kbase + s) * BK;
#pragma unroll
        for (int i = 0; i < TOT / 256; i++) {
            int c = tid + i * 256;
            const u16* src; u32 tb; int local, rowbase;
            if (c < CPA) { src = Ah; tb = sb;          local = c;       rowbase = bm; }
            else         { src = Bh; tb = sb + ABYTES; local = c - CPA; rowbase = bn; }
            int row = local >> 3, c16 = local & 7;
            cp16(tb + swz((u32)(row * ROWB + c16 * 16)),
                 src + (size_t)(rowbase + row) * KROW + k0 + c16 * 8);
        }
    };

    float acc[4][8][4];
#pragma unroll
    for (int a = 0; a < 4; a++)
#pragma unroll
        for (int b = 0; b < 8; b++)
#pragma unroll
            for (int k = 0; k < 4; k++) acc[a][b][k] = 0.f;

    const u32 sx   = ((u32)(lane & 7)) << 4;
    const u32 aOff = (u32)((wm * 64 + (lane & 15)) * ROWB);
    const u32 aK   = ((u32)(lane >> 4)) << 4;
    const u32 bOff = (u32)((wn * 64 + lane) * ROWB);

    // double-buffered register fragments: [buf][...]
    u32 fa[2][4][4];          // A: 4 m-frags
    u32 fb[2][2][2][4];       // B: [half][b0/b1]

    // 3-stage prologue: two groups in flight
    load_stage(0, 0); cp_commit();
    load_stage(1, 1); cp_commit();

    for (int s = 0; s < S; s++) {
        const int cb = s % 3;
        cp_wait<1>();
        __syncthreads();
        if (s + 2 < S) load_stage(s + 2, (s + 2) % 3);
        cp_commit();                  // unconditional: uniform group count

        const u32 sb = smem0 + (u32)cb * STAGE;
        const u32 sAh = sb, sBh = sb + ABYTES;

        // fragment loader for ks-step `ks` into buffer `fbuf`
        auto frag_ld = [&](int ks, int fbuf) {
            const u32 ko  = (((u32)(ks * 32) + aK) ^ sx);
            const u32 k0o = (((u32)(ks * 32)) ^ sx);
            const u32 k1o = (((u32)(ks * 32 + 16)) ^ sx);
#pragma unroll
            for (int mf = 0; mf < 4; mf++)
                ldsm4(fa[fbuf][mf], sAh + aOff + (u32)(mf * 16 * ROWB) + ko);
#pragma unroll
            for (int half = 0; half < 2; half++) {
                const u32 bo = bOff + (u32)(half * 32 * ROWB);
                ldsm4(fb[fbuf][half][0], sBh + bo + k0o);
                ldsm4(fb[fbuf][half][1], sBh + bo + k1o);
            }
        };

        frag_ld(0, 0);                // prime pipeline (exposed once/stage)
#pragma unroll
        for (int ks = 0; ks < BK / 16; ks++) {
            const int cur = ks & 1, nxt = cur ^ 1;
            if (ks + 1 < BK / 16) frag_ld(ks + 1, nxt);   // hide under MMAs
#pragma unroll
            for (int half = 0; half < 2; half++)
#pragma unroll
                for (int mf = 0; mf < 4; mf++)
#pragma unroll
                    for (int nf = 0; nf < 4; nf++)
                        mma_f16(acc[mf][half * 4 + nf], fa[cur][mf],
                                fb[cur][half][0][nf], fb[cur][half][1][nf]);
        }
    }

    // ---- fused epilogue ----
    constexpr int OST = (EPI == 1) ? O_DIM : L_DIM;
    float* PART = (EPI == 0) ? OF1 + (size_t)blockIdx.z * ZN : nullptr;
#pragma unroll
    for (int mf = 0; mf < 4; mf++) {
#pragma unroll
        for (int nfa = 0; nfa < 8; nfa++) {
            int r0 = bm + wm * 64 + mf * 16 + (lane >> 2);
            int cc = bn + wn * 64 + (nfa >> 2) * 32 + (nfa & 3) * 8 + (lane & 3) * 2;
#pragma unroll
            for (int h = 0; h < 2; h++) {
                int r = r0 + h * 8;
                float d0 = acc[mf][nfa][2 * h], d1 = acc[mf][nfa][2 * h + 1];
                size_t off = (size_t)r * OST + cc;
                if (EPI == 1) {
                    float2 xv = *(const float2*)(X + off);
                    float p0 = tanhf(d0), p1 = tanhf(d1);
                    float g0 = (1.f - p0 * p0) * (xv.x - p0);
                    float g1 = (1.f - p1 * p1) * (xv.y - p1);
                    *(u32*)(Oh + off) = (u32)f2h(g0) | ((u32)f2h(g1) << 16);
                } else {
                    *(float2*)(PART + off) = make_float2(d0, d1);
                }
            }
        }
    }
}

// -------- reduce split-K partials + fused z-update (deterministic order) ----
__global__ void reduce_z(const float* __restrict__ part, const float* __restrict__ mu,
                         float* __restrict__ zf, u16* __restrict__ zh,
                         float* __restrict__ out) {
    constexpr int ZN = B_DIM * L_DIM;
    int i = (blockIdx.x * blockDim.x + threadIdx.x) * 2;
    int l = i & (L_DIM - 1);
    float2 p0 = *(const float2*)(part + i);
    float2 p1 = *(const float2*)(part + ZN + i);
    float2 p2 = *(const float2*)(part + 2 * ZN + i);
    float2 p3 = *(const float2*)(part + 3 * ZN + i);
    float dx = (p0.x + p1.x) + (p2.x + p3.x);
    float dy = (p0.y + p1.y) + (p2.y + p3.y);
    float2 zv = *(const float2*)(zf + i);
    float2 mv = *(const float2*)(mu + l);
    float s0 = (float)((zv.x > 0.f) - (zv.x < 0.f));
    float s1 = (float)((zv.y > 0.f) - (zv.y < 0.f));
    float zn0 = zv.x - INF_LR * ((zv.x - mv.x) - dx + SPARSE_Z * s0);
    float zn1 = zv.y - INF_LR * ((zv.y - mv.y) - dy + SPARSE_Z * s1);
    *(float2*)(zf + i) = make_float2(zn0, zn1);
    *(u32*)(zh + i) = (u32)f2h(zn0) | ((u32)f2h(zn1) << 16);
    if (out) *(float2*)(out + i) = make_float2(zn0, zn1);
}

// ---------------- launch ----------------
extern "C" void kernel_launch(void* const* d_in, const int* in_sizes, int n_in,
                              void* d_out, int out_size) {
    const float* x  = (const float*)d_in[0];   // [B, O]
    const float* W  = (const float*)d_in[1];   // [O, L]
    const float* mu = (const float*)d_in[2];   // [L]
    // d_in[3] = inf_iters (device scalar; fixed at 20 by the problem spec)
    float* out = (float*)d_out;                // [B, L]

    u16 *Wh, *WTh, *Gh, *zh;
    float *zf, *part;
    cudaGetSymbolAddress((void**)&Wh,   g_Wh);
    cudaGetSymbolAddress((void**)&WTh,  g_WTh);
    cudaGetSymbolAddress((void**)&Gh,   g_Gh);
    cudaGetSymbolAddress((void**)&zf,   g_zf);
    cudaGetSymbolAddress((void**)&zh,   g_zh);
    cudaGetSymbolAddress((void**)&part, g_part);

    constexpr int STAGE = 128 * 128 + 256 * 128;   // 49152 B
    constexpr int SMEM  = 3 * STAGE + 256;         // 147712 B (3-stage ring)

    cudaFuncSetAttribute(gemm_big<1, L_DIM, L_DIM>,
                         cudaFuncAttributeMaxDynamicSharedMemorySize, SMEM);
    cudaFuncSetAttribute(gemm_big<0, O_DIM, 1024>,
                         cudaFuncAttributeMaxDynamicSharedMemorySize, SMEM);

    prep_w<<<dim3(L_DIM / 32, O_DIM / 32), dim3(32, 8)>>>(W, Wh, WTh);
    init_z<<<(B_DIM * L_DIM) / 256, 256>>>(mu, zf, zh);

    for (int it = 0; it < N_ITERS; ++it) {
        // GEMM1: C[b,o] = z @ W^T; fused tanh-deriv epilogue -> G (fp16)
        gemm_big<1, L_DIM, L_DIM>
            <<<dim3(O_DIM / 256, B_DIM / 128, 1), 256, SMEM>>>(
                zh, Wh, x, Gh, nullptr);

        // GEMM2: partial[b,l] per K-split of G @ W (B-operand = WT[l,o])
        gemm_big<0, O_DIM, 1024>
            <<<dim3(L_DIM / 256, B_DIM / 128, 4), 256, SMEM>>>(
                Gh, WTh, nullptr, nullptr, part);

        // deterministic 4-way reduce + fused z update (full-chip parallel)
        reduce_z<<<(B_DIM * L_DIM / 2) / 256, 256>>>(
            part, mu, zf, zh, (it == N_ITERS - 1) ? out : nullptr);
    }
}

// round 17
// speedup vs baseline: 1.0386x; 1.0386x over previous
#include <cuda_runtime.h>
#include <cuda_fp16.h>
#include <cstdint>
#include <stddef.h>
#include <math.h>

#define B_DIM 1024
#define L_DIM 1024
#define O_DIM 4096
#define N_ITERS 20
#define INF_LR   0.01f
#define SPARSE_Z 1e-3f

typedef unsigned short u16;
typedef uint32_t u32;

// ---------------- scratch (no cudaMalloc allowed) ----------------
__device__ u16   g_Wh  [O_DIM * L_DIM];
__device__ u16   g_WTh [L_DIM * O_DIM];
__device__ u16   g_Gh  [B_DIM * O_DIM];
__device__ float g_zf  [B_DIM * L_DIM];
__device__ u16   g_zh  [B_DIM * L_DIM];
__device__ float g_part[4 * B_DIM * L_DIM];   // split-K partials (16MB)
__device__ float g_p0  [O_DIM];               // iter-0 row prediction tanh(mu@W^T)

// ---------------- helpers ----------------
__device__ __forceinline__ u32 smem_u32(const void* p) {
    u32 a;
    asm("{ .reg .u64 t; cvta.to.shared.u64 t, %1; cvt.u32.u64 %0, t; }" : "=r"(a) : "l"(p));
    return a;
}
__device__ __forceinline__ void cp16(u32 dst, const void* src) {
    asm volatile("cp.async.cg.shared.global [%0], [%1], 16;" :: "r"(dst), "l"(src));
}
__device__ __forceinline__ void cp_commit() { asm volatile("cp.async.commit_group;"); }
template <int N> __device__ __forceinline__ void cp_wait() {
    asm volatile("cp.async.wait_group %0;" :: "n"(N));
}
__device__ __forceinline__ void ldsm4(u32* r, u32 a) {
    asm volatile("ldmatrix.sync.aligned.m8n8.x4.shared.b16 {%0,%1,%2,%3}, [%4];"
                 : "=r"(r[0]), "=r"(r[1]), "=r"(r[2]), "=r"(r[3]) : "r"(a));
}
__device__ __forceinline__ void mma_f16(float* d, const u32* a, u32 b0, u32 b1) {
    asm volatile(
        "mma.sync.aligned.m16n8k16.row.col.f32.f16.f16.f32 "
        "{%0,%1,%2,%3},{%4,%5,%6,%7},{%8,%9},{%0,%1,%2,%3};"
        : "+f"(d[0]), "+f"(d[1]), "+f"(d[2]), "+f"(d[3])
        : "r"(a[0]), "r"(a[1]), "r"(a[2]), "r"(a[3]), "r"(b0), "r"(b1));
}
__device__ __forceinline__ u16 f2h(float v) {
    return __half_as_ushort(__float2half_rn(v));
}
__device__ __forceinline__ u32 swz(u32 off) { return off ^ ((off >> 3) & 0x70u); }

// ---------------- one-time prep ----------------
__global__ void prep_w(const float* __restrict__ W,
                       u16* __restrict__ Wh, u16* __restrict__ WTh) {
    __shared__ float t[32][33];
    int tx = threadIdx.x, ty = threadIdx.y;
    int lx = blockIdx.x * 32, oy = blockIdx.y * 32;
#pragma unroll
    for (int r = 0; r < 32; r += 8) {
        size_t idx = (size_t)(oy + ty + r) * L_DIM + lx + tx;
        float v = W[idx];
        Wh[idx] = f2h(v);
        t[ty + r][tx] = v;
    }
    __syncthreads();
#pragma unroll
    for (int r = 0; r < 32; r += 8) {
        float v = t[tx][ty + r];
        size_t idx = (size_t)(lx + ty + r) * O_DIM + oy + tx;
        WTh[idx] = f2h(v);
    }
}

__global__ void init_z(const float* __restrict__ mu, float* __restrict__ zf,
                       u16* __restrict__ zh) {
    int i = blockIdx.x * blockDim.x + threadIdx.x;
    float v = mu[i & (L_DIM - 1)];
    zf[i] = v;
    zh[i] = f2h(v);
}

// ---- iter-0 shortcut: z0 = broadcast(mu) makes every GEMM1 row identical ----
// pref[o] = tanh( sum_l mu[l] * W[o,l] ), fp32-exact. One warp per o.
__global__ void pred0_kernel(const float* __restrict__ W,
                             const float* __restrict__ mu,
                             float* __restrict__ pref) {
    int o = blockIdx.x * 8 + (threadIdx.x >> 5);
    int lane = threadIdx.x & 31;
    const float* row = W + (size_t)o * L_DIM;
    float s = 0.f;
#pragma unroll
    for (int l = lane * 4; l < L_DIM; l += 128) {
        float4 w4 = *(const float4*)(row + l);
        float4 m4 = *(const float4*)(mu + l);
        s += w4.x * m4.x + w4.y * m4.y + w4.z * m4.z + w4.w * m4.w;
    }
#pragma unroll
    for (int d = 16; d > 0; d >>= 1)
        s += __shfl_xor_sync(0xffffffffu, s, d);
    if (lane == 0) pref[o] = tanhf(s);
}

// G0[b,o] = (1 - p^2) * (x[b,o] - p), p = pref[o]; write fp16.
__global__ void g0_kernel(const float* __restrict__ x,
                          const float* __restrict__ pref,
                          u16* __restrict__ Gh) {
    int i = (blockIdx.x * blockDim.x + threadIdx.x) * 2;
    int o = i & (O_DIM - 1);
    float2 pv = *(const float2*)(pref + o);
    float2 xv = *(const float2*)(x + i);
    float g0 = (1.f - pv.x * pv.x) * (xv.x - pv.x);
    float g1 = (1.f - pv.y * pv.y) * (xv.y - pv.y);
    *(u32*)(Gh + i) = (u32)f2h(g0) | ((u32)f2h(g1) << 16);
}

// ---- fp16 GEMM, CTA 128x256 (256 thr, 2x4 warps, warp tile 64x64) ----------
// EXACT R11 core (best measured config: 2-stage 96KB cp.async ring, BK=64).
// EPI=1: p=tanh(C); g=(1-p^2)*(X-p); write g as fp16 (Oh).
// EPI=0: write raw fp32 partial to OF1 + blockIdx.z*(B*L).
template <int EPI, int KROW, int KLEN>
__global__ void __launch_bounds__(256, 1)
gemm_big(const u16* __restrict__ Ah, const u16* __restrict__ Bh,
         const float* __restrict__ X,
         u16* __restrict__ Oh, float* __restrict__ OF1) {
    constexpr int BM = 128, BN = 256, BK = 64, ROWB = 128;
    constexpr int ABYTES = BM * ROWB;          // 16384
    constexpr int BBYTES = BN * ROWB;          // 32768
    constexpr int STAGE  = ABYTES + BBYTES;    // 49152
    constexpr int CPA = ABYTES / 16, CPB = BBYTES / 16;
    constexpr int TOT = CPA + CPB;             // 3072
    constexpr int S = KLEN / BK;               // 16
    constexpr int ZN = B_DIM * L_DIM;

    extern __shared__ char sraw[];
    const u32 smem0 = (smem_u32(sraw) + 127u) & ~127u;

    const int tid = threadIdx.x, lane = tid & 31, wid = tid >> 5;
    const int wm = wid >> 2, wn = wid & 3;     // 2 x 4 warps, warp tile 64x64
    const int bm = blockIdx.y * BM, bn = blockIdx.x * BN;
    const int kbase = blockIdx.z * S;

    auto load_stage = [&](int s, int buf) {
        const u32 sb = smem0 + (u32)buf * STAGE;
        const int k0 = (kbase + s) * BK;
#pragma unroll
        for (int i = 0; i < TOT / 256; i++) {
            int c = tid + i * 256;
            const u16* src; u32 tb; int local, rowbase;
            if (c < CPA) { src = Ah; tb = sb;          local = c;       rowbase = bm; }
            else         { src = Bh; tb = sb + ABYTES; local = c - CPA; rowbase = bn; }
            int row = local >> 3, c16 = local & 7;
            cp16(tb + swz((u32)(row * ROWB + c16 * 16)),
                 src + (size_t)(rowbase + row) * KROW + k0 + c16 * 8);
        }
    };

    float acc[4][8][4];
#pragma unroll
    for (int a = 0; a < 4; a++)
#pragma unroll
        for (int b = 0; b < 8; b++)
#pragma unroll
            for (int k = 0; k < 4; k++) acc[a][b][k] = 0.f;

    const u32 sx   = ((u32)(lane & 7)) << 4;
    const u32 aOff = (u32)((wm * 64 + (lane & 15)) * ROWB);
    const u32 aK   = ((u32)(lane >> 4)) << 4;
    const u32 bOff = (u32)((wn * 64 + lane) * ROWB);

    load_stage(0, 0); cp_commit();

    int cbuf = 0, lbuf = 1;
    for (int s = 0; s < S; s++) {
        cp_wait<0>();
        __syncthreads();
        if (s + 1 < S) load_stage(s + 1, lbuf);
        cp_commit();
        lbuf ^= 1;

        const u32 sb = smem0 + (u32)cbuf * STAGE;
        const u32 sAh = sb, sBh = sb + ABYTES;
#pragma unroll
        for (int ks = 0; ks < BK / 16; ks++) {
            const u32 ko  = (((u32)(ks * 32) + aK) ^ sx);
            const u32 k0o = (((u32)(ks * 32)) ^ sx);
            const u32 k1o = (((u32)(ks * 32 + 16)) ^ sx);

            u32 ah[4][4];
#pragma unroll
            for (int mf = 0; mf < 4; mf++)
                ldsm4(ah[mf], sAh + aOff + (u32)(mf * 16 * ROWB) + ko);
#pragma unroll
            for (int half = 0; half < 2; half++) {
                const u32 bo = bOff + (u32)(half * 32 * ROWB);
                u32 b0[4], b1[4];
                ldsm4(b0, sBh + bo + k0o);
                ldsm4(b1, sBh + bo + k1o);
#pragma unroll
                for (int mf = 0; mf < 4; mf++)
#pragma unroll
                    for (int nf = 0; nf < 4; nf++)
                        mma_f16(acc[mf][half * 4 + nf], ah[mf], b0[nf], b1[nf]);
            }
        }
        cbuf ^= 1;
    }

    // ---- fused epilogue ----
    constexpr int OST = (EPI == 1) ? O_DIM : L_DIM;
    float* PART = (EPI == 0) ? OF1 + (size_t)blockIdx.z * ZN : nullptr;
#pragma unroll
    for (int mf = 0; mf < 4; mf++) {
#pragma unroll
        for (int nfa = 0; nfa < 8; nfa++) {
            int r0 = bm + wm * 64 + mf * 16 + (lane >> 2);
            int cc = bn + wn * 64 + (nfa >> 2) * 32 + (nfa & 3) * 8 + (lane & 3) * 2;
#pragma unroll
            for (int h = 0; h < 2; h++) {
                int r = r0 + h * 8;
                float d0 = acc[mf][nfa][2 * h], d1 = acc[mf][nfa][2 * h + 1];
                size_t off = (size_t)r * OST + cc;
                if (EPI == 1) {
                    float2 xv = *(const float2*)(X + off);
                    float p0 = tanhf(d0), p1 = tanhf(d1);
                    float g0 = (1.f - p0 * p0) * (xv.x - p0);
                    float g1 = (1.f - p1 * p1) * (xv.y - p1);
                    *(u32*)(Oh + off) = (u32)f2h(g0) | ((u32)f2h(g1) << 16);
                } else {
                    *(float2*)(PART + off) = make_float2(d0, d1);
                }
            }
        }
    }
}

// -------- reduce split-K partials + fused z-update (deterministic order) ----
__global__ void reduce_z(const float* __restrict__ part, const float* __restrict__ mu,
                         float* __restrict__ zf, u16* __restrict__ zh,
                         float* __restrict__ out) {
    constexpr int ZN = B_DIM * L_DIM;
    int i = (blockIdx.x * blockDim.x + threadIdx.x) * 2;
    int l = i & (L_DIM - 1);
    float2 p0 = *(const float2*)(part + i);
    float2 p1 = *(const float2*)(part + ZN + i);
    float2 p2 = *(const float2*)(part + 2 * ZN + i);
    float2 p3 = *(const float2*)(part + 3 * ZN + i);
    float dx = (p0.x + p1.x) + (p2.x + p3.x);
    float dy = (p0.y + p1.y) + (p2.y + p3.y);
    float2 zv = *(const float2*)(zf + i);
    float2 mv = *(const float2*)(mu + l);
    float s0 = (float)((zv.x > 0.f) - (zv.x < 0.f));
    float s1 = (float)((zv.y > 0.f) - (zv.y < 0.f));
    float zn0 = zv.x - INF_LR * ((zv.x - mv.x) - dx + SPARSE_Z * s0);
    float zn1 = zv.y - INF_LR * ((zv.y - mv.y) - dy + SPARSE_Z * s1);
    *(float2*)(zf + i) = make_float2(zn0, zn1);
    *(u32*)(zh + i) = (u32)f2h(zn0) | ((u32)f2h(zn1) << 16);
    if (out) *(float2*)(out + i) = make_float2(zn0, zn1);
}

// ---------------- launch ----------------
extern "C" void kernel_launch(void* const* d_in, const int* in_sizes, int n_in,
                              void* d_out, int out_size) {
    const float* x  = (const float*)d_in[0];   // [B, O]
    const float* W  = (const float*)d_in[1];   // [O, L]
    const float* mu = (const float*)d_in[2];   // [L]
    // d_in[3] = inf_iters (device scalar; fixed at 20 by the problem spec)
    float* out = (float*)d_out;                // [B, L]

    u16 *Wh, *WTh, *Gh, *zh;
    float *zf, *part, *p0;
    cudaGetSymbolAddress((void**)&Wh,   g_Wh);
    cudaGetSymbolAddress((void**)&WTh,  g_WTh);
    cudaGetSymbolAddress((void**)&Gh,   g_Gh);
    cudaGetSymbolAddress((void**)&zf,   g_zf);
    cudaGetSymbolAddress((void**)&zh,   g_zh);
    cudaGetSymbolAddress((void**)&part, g_part);
    cudaGetSymbolAddress((void**)&p0,   g_p0);

    constexpr int STAGE = 128 * 128 + 256 * 128;   // 49152 B
    constexpr int SMEM  = 2 * STAGE + 256;         // 98560 B

    cudaFuncSetAttribute(gemm_big<1, L_DIM, L_DIM>,
                         cudaFuncAttributeMaxDynamicSharedMemorySize, SMEM);
    cudaFuncSetAttribute(gemm_big<0, O_DIM, 1024>,
                         cudaFuncAttributeMaxDynamicSharedMemorySize, SMEM);

    prep_w<<<dim3(L_DIM / 32, O_DIM / 32), dim3(32, 8)>>>(W, Wh, WTh);
    init_z<<<(B_DIM * L_DIM) / 256, 256>>>(mu, zf, zh);

    for (int it = 0; it < N_ITERS; ++it) {
        if (it == 0) {
            // z0 = broadcast(mu): GEMM1 rows are identical -> fp32 mat-vec +
            // elementwise tanh-deriv epilogue (exact; replaces a full GEMM)
            pred0_kernel<<<O_DIM / 8, 256>>>(W, mu, p0);
            g0_kernel<<<(B_DIM * O_DIM / 2) / 256, 256>>>(x, p0, Gh);
        } else {
            // GEMM1: C[b,o] = z @ W^T; fused tanh-deriv epilogue -> G (fp16)
            gemm_big<1, L_DIM, L_DIM>
                <<<dim3(O_DIM / 256, B_DIM / 128, 1), 256, SMEM>>>(
                    zh, Wh, x, Gh, nullptr);
        }

        // GEMM2: partial[b,l] per K-split of G @ W (B-operand = WT[l,o])
        gemm_big<0, O_DIM, 1024>
            <<<dim3(L_DIM / 256, B_DIM / 128, 4), 256, SMEM>>>(
                Gh, WTh, nullptr, nullptr, part);

        // deterministic 4-way reduce + fused z update (full-chip parallel)
        reduce_z<<<(B_DIM * L_DIM / 2) / 256, 256>>>(
            part, mu, zf, zh, (it == N_ITERS - 1) ? out : nullptr);
    }
}